// round 3
// baseline (speedup 1.0000x reference)
#include <cuda_runtime.h>

// ---------------- problem constants ----------------
constexpr int   kNumNodes   = 120000;
constexpr int   kNumMovable = 100000;
constexpr int   kNumNets    = 100000;
constexpr int   kNumPins    = 400000;
constexpr int   kNbx = 256, kNby = 256;
constexpr int   kMap = kNbx * kNby;
constexpr float kBsx = 1000.0f / 256.0f;      // 3.90625 (exact in fp32)
constexpr float kBsy = 1000.0f / 256.0f;
constexpr float kInvBsx = 256.0f / 1000.0f;
constexpr float kInvBsy = 256.0f / 1000.0f;
constexpr float kEps = 1e-6f;
constexpr float kBinArea = kBsx * kBsy;
constexpr float kHNorm = 1.0f / (kBinArea * 1.5f);   // UNIT_H_CAP
constexpr float kVNorm = 1.0f / (kBinArea * 1.5f);   // UNIT_V_CAP

// ---------------- device scratch (no allocs allowed) ----------------
// g_scat layout: [map(H=0,V=1)][term(A,Bx,By,P)][x*256+y]  (x-major)
__device__ float g_scat[8 * kMap];
// g_T layout: [T1h, T2h, T1v, T2v], each y-major: [y*256+x]
__device__ float g_T[4 * kMap];
// util, y-major: [y*256+x]
__device__ float g_util[kMap];

// ---------------- kernels ----------------
__global__ void zero_kernel() {
    int i = blockIdx.x * blockDim.x + threadIdx.x;
    float4* p = reinterpret_cast<float4*>(g_scat);
    if (i < (8 * kMap) / 4) p[i] = make_float4(0.f, 0.f, 0.f, 0.f);
}

// Scatter one signed corner term of the clamp-overlap decomposition.
//   A  at (ka-1, kb-1) weight bs*bs   (2D suffix sum recovers)
//   Bx at (ka-1, kb  ) weight bs*fb   (suffix sum along x)
//   By at (ka,   kb-1) weight fa*bs   (suffix sum along y)
//   P  at (ka,   kb  ) weight fa*fb   (no scan)
__device__ __forceinline__ void scatter_corner(float* base, int ka, int kb,
                                               float fa, float fb, float v) {
    float* A  = base;
    float* Bx = base + kMap;
    float* By = base + 2 * kMap;
    float* P  = base + 3 * kMap;
    if (ka > 0 && kb > 0) atomicAdd(&A[(ka - 1) * kNby + (kb - 1)], v * (kBsx * kBsy));
    if (ka > 0)           atomicAdd(&Bx[(ka - 1) * kNby + kb],      v * kBsx * fb);
    if (kb > 0)           atomicAdd(&By[ka * kNby + (kb - 1)],      v * fa * kBsy);
    atomicAdd(&P[ka * kNby + kb], v * fa * fb);
}

__global__ void net_kernel(const float* __restrict__ pin_pos,
                           const int* __restrict__ netpin_start,
                           const int* __restrict__ flat_netpin) {
    int n = blockIdx.x * blockDim.x + threadIdx.x;
    if (n >= kNumNets) return;
    int s = netpin_start[n];
    int e = netpin_start[n + 1];
    if (e <= s) return;   // empty net -> invalid -> zero contribution

    float xmin = 1e30f, xmax = -1e30f, ymin = 1e30f, ymax = -1e30f;
    for (int p = s; p < e; ++p) {
        int q   = __ldg(&flat_netpin[p]);
        float px = __ldg(&pin_pos[q]);
        float py = __ldg(&pin_pos[kNumPins + q]);
        xmin = fminf(xmin, px); xmax = fmaxf(xmax, px);
        ymin = fminf(ymin, py); ymax = fmaxf(ymax, py);
    }
    float span_x = xmax - xmin;
    float span_y = ymax - ymin;
    float ch = (span_y > kEps) ? (1.0f / fmaxf(span_y, kEps)) : 0.0f;
    float cv = (span_x > kEps) ? (1.0f / fmaxf(span_x, kEps)) : 0.0f;
    if (ch == 0.0f && cv == 0.0f) return;

    float vx[2] = {xmin, xmax};
    float vy[2] = {ymin, ymax};
    int   kx[2], ky[2];
    float fx[2], fy[2];
#pragma unroll
    for (int i = 0; i < 2; ++i) {
        int k = __float2int_rd(vx[i] * kInvBsx);
        k = min(max(k, 0), kNbx - 1);
        kx[i] = k;
        fx[i] = fminf(fmaxf(vx[i] - (float)k * kBsx, 0.0f), kBsx);
        k = __float2int_rd(vy[i] * kInvBsy);
        k = min(max(k, 0), kNby - 1);
        ky[i] = k;
        fy[i] = fminf(fmaxf(vy[i] - (float)k * kBsy, 0.0f), kBsy);
    }

    // corners: (xmax,ymax)+  (xmax,ymin)-  (xmin,ymax)-  (xmin,ymin)+
#pragma unroll
    for (int i = 0; i < 2; ++i) {
#pragma unroll
        for (int j = 0; j < 2; ++j) {
            float sgn = (i == j) ? 1.0f : -1.0f;
            if (ch != 0.0f)
                scatter_corner(g_scat,            kx[i], ky[j], fx[i], fy[j], sgn * ch);
            if (cv != 0.0f)
                scatter_corner(g_scat + 4 * kMap, kx[i], ky[j], fx[i], fy[j], sgn * cv);
        }
    }
}

// Dual inclusive suffix scan over a 256-thread block (tid = element index,
// suffix = sum over indices >= tid). Two independent values scanned at once.
__device__ __forceinline__ void dual_block_suffix_scan(float v1, float v2,
                                                       float& o1, float& o2) {
    __shared__ float s1[8], s2[8];
    int tid  = threadIdx.x;
    int lane = tid & 31;
    int w    = tid >> 5;
    float x1 = v1, x2 = v2;
#pragma unroll
    for (int o = 1; o < 32; o <<= 1) {
        float t1 = __shfl_down_sync(0xffffffffu, x1, o);
        float t2 = __shfl_down_sync(0xffffffffu, x2, o);
        if (lane + o < 32) { x1 += t1; x2 += t2; }
    }
    if (lane == 0) { s1[w] = x1; s2[w] = x2; }   // warp suffix totals
    __syncthreads();
    float a1 = 0.f, a2 = 0.f;
#pragma unroll
    for (int j = 0; j < 8; ++j) {
        if (j > w) { a1 += s1[j]; a2 += s2[j]; }
    }
    o1 = x1 + a1;
    o2 = x2 + a2;
}

// Suffix-sum along y (per map m, per x-row): T1 = Sy(A)+Bx, T2 = Sy(By)+P
// One block per (m, x) row; thread = y. Reads coalesced (x-major input),
// writes TRANSPOSED into y-major g_T (uncoalesced stores are cheap).
__global__ void scan_y_kernel() {
    int b = blockIdx.x;           // 0..511
    int m = b >> 8;
    int x = b & 255;
    int y = threadIdx.x;
    const float* A  = g_scat + m * 4 * kMap + x * kNby;
    const float* Bx = A + kMap;
    const float* By = A + 2 * kMap;
    const float* P  = A + 3 * kMap;
    float sA, sBy;
    dual_block_suffix_scan(A[y], By[y], sA, sBy);
    float* T1 = g_T + m * 2 * kMap;      // y-major
    float* T2 = T1 + kMap;
    int ti = y * kNbx + x;
    T1[ti] = sA + Bx[y];
    T2[ti] = sBy + P[y];
}

// Suffix-sum along x (per y column), fuse H,V and util map.
// One block per y; thread = x. Fully coalesced loads & stores (y-major).
__global__ void scan_x_util_kernel() {
    int y = blockIdx.x;
    int x = threadIdx.x;
    int idx = y * kNbx + x;
    float t1h = g_T[idx];
    float t2h = g_T[kMap + idx];
    float t1v = g_T[2 * kMap + idx];
    float t2v = g_T[3 * kMap + idx];
    float sH, sV;
    dual_block_suffix_scan(t1h, t1v, sH, sV);
    float H = sH + t2h;
    float V = sV + t2v;
    float u = fmaxf(H * kHNorm, V * kVNorm);
    u = fminf(fmaxf(u, 0.5f), 2.0f);
    g_util[idx] = u;      // y-major
}

__global__ void node_kernel(const float* __restrict__ pos,
                            const float* __restrict__ nsx,
                            const float* __restrict__ nsy,
                            float* __restrict__ out) {
    int m = blockIdx.x * blockDim.x + threadIdx.x;
    if (m >= kNumMovable) return;
    float xl = pos[m];
    float yl = pos[kNumNodes + m];
    float xh = xl + nsx[m];
    float yh = yl + nsy[m];
    int bx0 = min(max(__float2int_rd(xl * kInvBsx), 0), kNbx - 1);
    int bx1 = min(max(__float2int_rd(xh * kInvBsx), 0), kNbx - 1);
    int by0 = min(max(__float2int_rd(yl * kInvBsy), 0), kNby - 1);
    int by1 = min(max(__float2int_rd(yh * kInvBsy), 0), kNby - 1);
    float acc = 0.0f;
    for (int yb = by0; yb <= by1; ++yb) {
        float ey = (float)yb * kBsy;
        float oy = fminf(yh, ey + kBsy) - fmaxf(yl, ey);
        oy = fmaxf(oy, 0.0f);
        const float* urow = g_util + yb * kNbx;   // y-major util
        for (int x = bx0; x <= bx1; ++x) {
            float ex = (float)x * kBsx;
            float ox = fminf(xh, ex + kBsx) - fmaxf(xl, ex);
            ox = fmaxf(ox, 0.0f);
            acc += ox * oy * urow[x];
        }
    }
    out[m] = acc;
}

// ---------------- launcher ----------------
extern "C" void kernel_launch(void* const* d_in, const int* in_sizes, int n_in,
                              void* d_out, int out_size) {
    const float* pos          = (const float*)d_in[0];
    const float* pin_pos      = (const float*)d_in[1];
    const float* node_size_x  = (const float*)d_in[2];
    const float* node_size_y  = (const float*)d_in[3];
    const int*   netpin_start = (const int*)d_in[4];
    const int*   flat_netpin  = (const int*)d_in[5];
    float*       out          = (float*)d_out;

    zero_kernel<<<(8 * kMap / 4 + 255) / 256, 256>>>();
    net_kernel<<<(kNumNets + 127) / 128, 128>>>(pin_pos, netpin_start, flat_netpin);
    scan_y_kernel<<<512, 256>>>();
    scan_x_util_kernel<<<256, 256>>>();
    node_kernel<<<(kNumMovable + 255) / 256, 256>>>(pos, node_size_x, node_size_y, out);
}

// round 4
// speedup vs baseline: 1.5863x; 1.5863x over previous
#include <cuda_runtime.h>

// ---------------- problem constants ----------------
constexpr int   kNumNodes   = 120000;
constexpr int   kNumMovable = 100000;
constexpr int   kNumNets    = 100000;
constexpr int   kNumPins    = 400000;
constexpr int   kNbx = 256, kNby = 256;
constexpr int   kMap = kNbx * kNby;
constexpr float kBsx = 1000.0f / 256.0f;      // 3.90625 (exact in fp32)
constexpr float kBsy = 1000.0f / 256.0f;
constexpr float kInvBsx = 256.0f / 1000.0f;
constexpr float kInvBsy = 256.0f / 1000.0f;
constexpr float kEps = 1e-6f;
constexpr float kBinArea = kBsx * kBsy;
constexpr float kHNorm = 1.0f / (kBinArea * 1.5f);   // UNIT_H_CAP
constexpr float kVNorm = 1.0f / (kBinArea * 1.5f);   // UNIT_V_CAP

// ---------------- device scratch (no allocs allowed) ----------------
// g_scat4[m * kMap + x*256 + y] = {A', Bx', By', P} for map m (H=0, V=1).
// All four corner terms of a net land at the SAME cell -> one red.v4.f32.
// Exclusive suffix scans recover the shifted planes.
// Zero-initialized at load; scan_y re-zeros it in place each run.
__device__ float4 g_scat4[2 * kMap];
// g_T layout: [U1h, U2h, U1v, U2v], each y-major: [y*256+x]
__device__ float g_T[4 * kMap];
// util, y-major: [y*256+x]
__device__ float g_util[kMap];

// one 16B vector reduction = 4 scalar atomic adds
__device__ __forceinline__ void red4(float4* p, float a, float b, float c, float d) {
    asm volatile("red.global.add.v4.f32 [%0], {%1, %2, %3, %4};"
                 :: "l"(p), "f"(a), "f"(b), "f"(c), "f"(d) : "memory");
}

__global__ void net_kernel(const float* __restrict__ pin_pos,
                           const int* __restrict__ netpin_start,
                           const int* __restrict__ flat_netpin) {
    int n = blockIdx.x * blockDim.x + threadIdx.x;
    if (n >= kNumNets) return;
    int s = netpin_start[n];
    int e = netpin_start[n + 1];
    if (e <= s) return;   // empty net -> invalid -> zero contribution

    float xmin = 1e30f, xmax = -1e30f, ymin = 1e30f, ymax = -1e30f;
    for (int p = s; p < e; ++p) {
        int q   = __ldg(&flat_netpin[p]);
        float px = __ldg(&pin_pos[q]);
        float py = __ldg(&pin_pos[kNumPins + q]);
        xmin = fminf(xmin, px); xmax = fmaxf(xmax, px);
        ymin = fminf(ymin, py); ymax = fmaxf(ymax, py);
    }
    float span_x = xmax - xmin;
    float span_y = ymax - ymin;
    float ch = (span_y > kEps) ? (1.0f / fmaxf(span_y, kEps)) : 0.0f;
    float cv = (span_x > kEps) ? (1.0f / fmaxf(span_x, kEps)) : 0.0f;
    if (ch == 0.0f && cv == 0.0f) return;

    float vx[2] = {xmin, xmax};
    float vy[2] = {ymin, ymax};
    int   kx[2], ky[2];
    float fx[2], fy[2];
#pragma unroll
    for (int i = 0; i < 2; ++i) {
        int k = __float2int_rd(vx[i] * kInvBsx);
        k = min(max(k, 0), kNbx - 1);
        kx[i] = k;
        fx[i] = fminf(fmaxf(vx[i] - (float)k * kBsx, 0.0f), kBsx);
        k = __float2int_rd(vy[i] * kInvBsy);
        k = min(max(k, 0), kNby - 1);
        ky[i] = k;
        fy[i] = fminf(fmaxf(vy[i] - (float)k * kBsy, 0.0f), kBsy);
    }

    // corners: (i==j) -> +, else -
#pragma unroll
    for (int i = 0; i < 2; ++i) {
#pragma unroll
        for (int j = 0; j < 2; ++j) {
            float sgn = (i == j) ? 1.0f : -1.0f;
            float fa = fx[i], fb = fy[j];
            int cell = kx[i] * kNby + ky[j];
            float wh = sgn * ch;
            float wv = sgn * cv;
            // {A'=v*bs*bs, Bx'=v*bs*fb, By'=v*fa*bs, P=v*fa*fb}
            red4(&g_scat4[cell],        wh * (kBsx * kBsy), wh * kBsx * fb,
                                        wh * fa * kBsy,     wh * fa * fb);
            red4(&g_scat4[kMap + cell], wv * (kBsx * kBsy), wv * kBsx * fb,
                                        wv * fa * kBsy,     wv * fa * fb);
        }
    }
}

// Dual inclusive suffix scan over a 256-thread block (tid = element index,
// suffix = sum over indices >= tid). Two independent values scanned at once.
__device__ __forceinline__ void dual_block_suffix_scan(float v1, float v2,
                                                       float& o1, float& o2) {
    __shared__ float s1[8], s2[8];
    int tid  = threadIdx.x;
    int lane = tid & 31;
    int w    = tid >> 5;
    float x1 = v1, x2 = v2;
#pragma unroll
    for (int o = 1; o < 32; o <<= 1) {
        float t1 = __shfl_down_sync(0xffffffffu, x1, o);
        float t2 = __shfl_down_sync(0xffffffffu, x2, o);
        if (lane + o < 32) { x1 += t1; x2 += t2; }
    }
    if (lane == 0) { s1[w] = x1; s2[w] = x2; }   // warp suffix totals
    __syncthreads();
    float a1 = 0.f, a2 = 0.f;
#pragma unroll
    for (int j = 0; j < 8; ++j) {
        if (j > w) { a1 += s1[j]; a2 += s2[j]; }
    }
    o1 = x1 + a1;
    o2 = x2 + a2;
}

// Per (m, x) row: U1 = SyExcl(A') + Bx',  U2 = SyExcl(By') + P.
// Reads one float4 per thread (coalesced), re-zeros the scatter array in
// place, writes U1/U2 transposed into y-major g_T.
__global__ void scan_y_kernel() {
    int b = blockIdx.x;           // 0..511
    int m = b >> 8;
    int x = b & 255;
    int y = threadIdx.x;
    int ci = m * kMap + x * kNby + y;
    float4 c = g_scat4[ci];
    g_scat4[ci] = make_float4(0.f, 0.f, 0.f, 0.f);
    float sA, sBy;
    dual_block_suffix_scan(c.x, c.z, sA, sBy);     // inclusive
    float U1 = (sA  - c.x) + c.y;                  // exclusive + Bx'
    float U2 = (sBy - c.z) + c.w;                  // exclusive + P
    float* T1 = g_T + m * 2 * kMap;                // y-major
    float* T2 = T1 + kMap;
    int ti = y * kNbx + x;
    T1[ti] = U1;
    T2[ti] = U2;
}

// Per y column: H = SxExcl(U1h) + U2h, V likewise; fuse util map.
// One block per y; thread = x. Fully coalesced (y-major).
__global__ void scan_x_util_kernel() {
    int y = blockIdx.x;
    int x = threadIdx.x;
    int idx = y * kNbx + x;
    float u1h = g_T[idx];
    float u2h = g_T[kMap + idx];
    float u1v = g_T[2 * kMap + idx];
    float u2v = g_T[3 * kMap + idx];
    float sH, sV;
    dual_block_suffix_scan(u1h, u1v, sH, sV);      // inclusive
    float H = (sH - u1h) + u2h;                    // exclusive + U2
    float V = (sV - u1v) + u2v;
    float u = fmaxf(H * kHNorm, V * kVNorm);
    u = fminf(fmaxf(u, 0.5f), 2.0f);
    g_util[idx] = u;      // y-major
}

__global__ void node_kernel(const float* __restrict__ pos,
                            const float* __restrict__ nsx,
                            const float* __restrict__ nsy,
                            float* __restrict__ out) {
    int m = blockIdx.x * blockDim.x + threadIdx.x;
    if (m >= kNumMovable) return;
    float xl = pos[m];
    float yl = pos[kNumNodes + m];
    float xh = xl + nsx[m];
    float yh = yl + nsy[m];
    int bx0 = min(max(__float2int_rd(xl * kInvBsx), 0), kNbx - 1);
    int bx1 = min(max(__float2int_rd(xh * kInvBsx), 0), kNbx - 1);
    int by0 = min(max(__float2int_rd(yl * kInvBsy), 0), kNby - 1);
    int by1 = min(max(__float2int_rd(yh * kInvBsy), 0), kNby - 1);
    float acc = 0.0f;
    for (int yb = by0; yb <= by1; ++yb) {
        float ey = (float)yb * kBsy;
        float oy = fminf(yh, ey + kBsy) - fmaxf(yl, ey);
        oy = fmaxf(oy, 0.0f);
        const float* urow = g_util + yb * kNbx;   // y-major util
        for (int x = bx0; x <= bx1; ++x) {
            float ex = (float)x * kBsx;
            float ox = fminf(xh, ex + kBsx) - fmaxf(xl, ex);
            ox = fmaxf(ox, 0.0f);
            acc += ox * oy * urow[x];
        }
    }
    out[m] = acc;
}

// ---------------- launcher ----------------
extern "C" void kernel_launch(void* const* d_in, const int* in_sizes, int n_in,
                              void* d_out, int out_size) {
    const float* pos          = (const float*)d_in[0];
    const float* pin_pos      = (const float*)d_in[1];
    const float* node_size_x  = (const float*)d_in[2];
    const float* node_size_y  = (const float*)d_in[3];
    const int*   netpin_start = (const int*)d_in[4];
    const int*   flat_netpin  = (const int*)d_in[5];
    float*       out          = (float*)d_out;

    net_kernel<<<(kNumNets + 255) / 256, 256>>>(pin_pos, netpin_start, flat_netpin);
    scan_y_kernel<<<512, 256>>>();
    scan_x_util_kernel<<<256, 256>>>();
    node_kernel<<<(kNumMovable + 255) / 256, 256>>>(pos, node_size_x, node_size_y, out);
}